// round 3
// baseline (speedup 1.0000x reference)
#include <cuda_runtime.h>

#define CHANNELS 512
#define BATCH    32
#define HW       4096
#define POS      7

#define OT 8
#define BT 8
#define STR 513

#define HEAD_BLOCKS 256                    // (64 o-tiles) x (4 b-tiles)
#define POS_BLOCKS  2
#define POOL_BLOCKS (BATCH * CHANNELS)
#define PRODUCERS   (POOL_BLOCKS + POS_BLOCKS)
#define NBLOCKS     (HEAD_BLOCKS + POS_BLOCKS + POOL_BLOCKS)

__device__ float g_pooled[BATCH * CHANNELS];
__device__ float g_P[CHANNELS];
__device__ int   g_count;   // zero-initialized; reset by last head block
__device__ int   g_done;

__global__ void __launch_bounds__(256) fused_kernel(
    const float* __restrict__ x,
    const float* __restrict__ pos,
    const float* __restrict__ conv_w,
    const float* __restrict__ conv_b,
    const float* __restrict__ gamma,
    const float* __restrict__ beta,
    const float* __restrict__ mean,
    const float* __restrict__ var,
    float* __restrict__ out)
{
    __shared__ float Wt[OT * STR];
    __shared__ float Pt[BT * STR];
    __shared__ float red[OT * BT * 4];

    const int t   = threadIdx.x;
    const int bid = blockIdx.x;

    if (bid >= HEAD_BLOCKS + POS_BLOCKS) {
        // ------------------- pool: one (b,c) row of 4096 floats -------------
        const int row = bid - (HEAD_BLOCKS + POS_BLOCKS);
        const float4* __restrict__ xr =
            reinterpret_cast<const float4*>(x + (size_t)row * HW);
        float s = 0.0f;
#pragma unroll
        for (int k = 0; k < 4; k++) {
            float4 v = __ldcs(&xr[t + k * 256]);   // streaming: keep L2 for W
            s += (v.x + v.y) + (v.z + v.w);
        }
#pragma unroll
        for (int o = 16; o; o >>= 1) s += __shfl_xor_sync(0xffffffffu, s, o);
        if ((t & 31) == 0) red[t >> 5] = s;
        __syncthreads();
        if (t == 0) {
            float tot = 0.0f;
#pragma unroll
            for (int i = 0; i < 8; i++) tot += red[i];
            g_pooled[row] = tot * (1.0f / HW);
            __threadfence();
            atomicAdd(&g_count, 1);
        }
    } else if (bid >= HEAD_BLOCKS) {
        // ------------------- pos-embed channel means ------------------------
        __shared__ float wx[POS];
        if (t < POS) wx[t] = 0.0f;
        __syncthreads();
        if (t < 64) {
            float src = (t + 0.5f) * (7.0f / 64.0f) - 0.5f;
            src = fminf(fmaxf(src, 0.0f), 6.0f);
            int j0 = (int)floorf(src);
            if (j0 > 5) j0 = 5;
            float f = src - (float)j0;
            atomicAdd(&wx[j0], 1.0f - f);
            atomicAdd(&wx[j0 + 1], f);
        }
        __syncthreads();

        const int c = (bid - HEAD_BLOCKS) * 256 + t;
        const float* __restrict__ pc = pos + c * (POS * POS);
        float P = 0.0f;
#pragma unroll
        for (int a = 0; a < POS; a++) {
            float r = 0.0f;
#pragma unroll
            for (int j = 0; j < POS; j++) r += wx[j] * pc[a * POS + j];
            P += wx[a] * r;
        }
        g_P[c] = P * (1.0f / HW);
        __threadfence();
        __syncthreads();
        if (t == 0) atomicAdd(&g_count, 1);
    } else {
        // ------------------- head: prefetch W, wait, matmul -----------------
        const int o0 = (bid & 63) * OT;
        const int b0 = (bid >> 6) * BT;

        // Prefetch W tile (independent of pool) — runs in the pool's shadow.
        {
            const float4* __restrict__ wsrc =
                reinterpret_cast<const float4*>(conv_w + (size_t)o0 * CHANNELS);
#pragma unroll
            for (int k = 0; k < 4; k++) {
                int i = t + k * 256;
                float4 v = wsrc[i];
                int row = i >> 7;
                int col = (i & 127) << 2;
                float* d = &Wt[row * STR + col];
                d[0] = v.x; d[1] = v.y; d[2] = v.z; d[3] = v.w;
            }
        }

        // Wait for all producers.
        if (t == 0) {
            while (atomicAdd(&g_count, 0) < PRODUCERS) __nanosleep(128);
        }
        __syncthreads();
        __threadfence();

        // Stage P tile (pooled + P), bypass L1 (written by other SMs).
        {
#pragma unroll
            for (int k = 0; k < 4; k++) {
                int i = t + k * 256;
                int row = i >> 7;
                int col = (i & 127) << 2;
                const float4 v = __ldcg(reinterpret_cast<const float4*>(
                    &g_pooled[(b0 + row) * CHANNELS + col]));
                const float4 p = __ldcg(reinterpret_cast<const float4*>(&g_P[col]));
                float* d = &Pt[row * STR + col];
                d[0] = v.x + p.x; d[1] = v.y + p.y;
                d[2] = v.z + p.z; d[3] = v.w + p.w;
            }
        }
        __syncthreads();

        const int o_l  = t & 7;
        const int b_l  = (t >> 3) & 7;
        const int part = t >> 6;

        const float* __restrict__ wr = &Wt[o_l * STR + part * 128];
        const float* __restrict__ pr = &Pt[b_l * STR + part * 128];
        float acc = 0.0f;
#pragma unroll 16
        for (int c = 0; c < 128; c++) acc += wr[c] * pr[c];

        red[(o_l * BT + b_l) * 4 + part] = acc;
        __syncthreads();

        if (t < OT * BT) {
            const int ol = t & 7;
            const int bl = t >> 3;
            const float* r = &red[(ol * BT + bl) * 4];
            float y = (r[0] + r[1]) + (r[2] + r[3]);
            const int o = o0 + ol;
            y += conv_b[o];
            y = gamma[o] * (y - mean[o]) * rsqrtf(var[o] + 1e-5f) + beta[o];
            out[(b0 + bl) * CHANNELS + o] = fmaxf(y, 0.0f);
        }
        __syncthreads();

        // Reset counters for the next (graph-replayed) launch.
        if (t == 0) {
            __threadfence();
            int d = atomicAdd(&g_done, 1);
            if (d == HEAD_BLOCKS - 1) {
                g_count = 0;
                g_done  = 0;
                __threadfence();
            }
        }
    }
}

extern "C" void kernel_launch(void* const* d_in, const int* in_sizes, int n_in,
                              void* d_out, int out_size) {
    const float* x      = (const float*)d_in[0];
    const float* pos    = (const float*)d_in[1];
    const float* conv_w = (const float*)d_in[2];
    const float* conv_b = (const float*)d_in[3];
    const float* gamma  = (const float*)d_in[4];
    const float* beta   = (const float*)d_in[5];
    const float* mean   = (const float*)d_in[6];
    const float* var    = (const float*)d_in[7];
    float* out = (float*)d_out;

    fused_kernel<<<NBLOCKS, 256>>>(x, pos, conv_w, conv_b,
                                   gamma, beta, mean, var, out);
}